// round 1
// baseline (speedup 1.0000x reference)
#include <cuda_runtime.h>
#include <math.h>

#define T_ 256
#define N_ 64
#define C_ 4096
#define L_ 32
#define S_ 65           // 2*L+1
#define BLANK_ 0
#define NEGV -1e30f

// Scratch (no allocations allowed): lp_ext[T][N][S] and per-batch nll
__device__ float g_lp_ext[T_ * N_ * S_];
__device__ float g_per_n[N_];

__device__ __forceinline__ float lae(float a, float b) {
    float m = fmaxf(a, b);
    return m + logf(expf(a - m) + expf(b - m));
}

// Kernel 1: per (t,n) row of 4096 -> logsumexp, then gather the 65 extended-label
// log-probs into g_lp_ext. One block (256 threads) per row; each thread holds 16
// values in registers so preds is read exactly once.
__global__ void __launch_bounds__(256) lse_gather_kernel(
    const float* __restrict__ preds, const int* __restrict__ targets)
{
    const int row = blockIdx.x;        // row = t*N + n  (preds is (T,N,C) row-major)
    const int n   = row % N_;
    const float* __restrict__ p = preds + (size_t)row * C_;
    const int tid = threadIdx.x;

    float v[16];
    const float4* __restrict__ p4 = (const float4*)p;
    #pragma unroll
    for (int k = 0; k < 4; k++) {
        float4 f = p4[tid + k * 256];
        v[k*4+0] = f.x; v[k*4+1] = f.y; v[k*4+2] = f.z; v[k*4+3] = f.w;
    }

    // block max
    float m = v[0];
    #pragma unroll
    for (int i = 1; i < 16; i++) m = fmaxf(m, v[i]);
    #pragma unroll
    for (int o = 16; o > 0; o >>= 1) m = fmaxf(m, __shfl_xor_sync(0xffffffffu, m, o));
    __shared__ float sm[8];
    if ((tid & 31) == 0) sm[tid >> 5] = m;
    __syncthreads();
    float bm = sm[0];
    #pragma unroll
    for (int i = 1; i < 8; i++) bm = fmaxf(bm, sm[i]);
    __syncthreads();   // sm reused below

    // block sum of exp
    float s = 0.0f;
    #pragma unroll
    for (int i = 0; i < 16; i++) s += expf(v[i] - bm);
    #pragma unroll
    for (int o = 16; o > 0; o >>= 1) s += __shfl_xor_sync(0xffffffffu, s, o);
    if ((tid & 31) == 0) sm[tid >> 5] = s;
    __syncthreads();
    float bs = sm[0];
    #pragma unroll
    for (int i = 1; i < 8; i++) bs += sm[i];

    const float lse = bm + logf(bs);

    // gather extended labels: even s -> blank(0), odd s -> targets[n][ (s-1)/2 ]
    if (tid < S_) {
        int label = (tid & 1) ? targets[n * L_ + (tid >> 1)] : BLANK_;
        g_lp_ext[row * S_ + tid] = p[label] - lse;   // L2 hit (row just streamed)
    }
}

// Kernel 2: CTC forward recursion. One block per batch element n; thread s owns
// state s. Double-buffered alpha in shared memory, one barrier per timestep.
__global__ void __launch_bounds__(96) ctc_forward_kernel(
    const int* __restrict__ targets,
    const int* __restrict__ pred_lengths,
    const int* __restrict__ target_lengths)
{
    const int n = blockIdx.x;
    const int s = threadIdx.x;          // 0..95, states are s < S_
    const int tl = target_lengths[n];
    const int pl = pred_lengths[n];
    const int Sv = 2 * tl + 1;

    __shared__ float buf[2][S_ + 2];    // +2 front padding (NEG) for s-1, s-2

    bool skip = false;
    if (s < S_ && (s & 1) && s >= 2) {
        int lab  = targets[n * L_ + (s >> 1)];
        int lab2 = targets[n * L_ + (s >> 1) - 1];
        skip = (lab != BLANK_) && (lab != lab2);
    }
    const bool valid = (s < Sv);

    if (threadIdx.x < 2) { buf[0][threadIdx.x] = NEGV; buf[1][threadIdx.x] = NEGV; }

    // alpha0
    if (s < S_) {
        float a0 = NEGV;
        if (s == 0)            a0 = g_lp_ext[n * S_ + 0];
        if (s == 1 && tl > 0)  a0 = g_lp_ext[n * S_ + 1];
        if (!valid)            a0 = NEGV;
        buf[0][s + 2] = a0;
    }
    __syncthreads();

    int cur = 0;
    for (int t = 1; t < T_; t++) {
        float nv = NEGV;
        if (s < S_) {
            float a1 = buf[cur][s + 2];
            float a2 = buf[cur][s + 1];
            float a3 = skip ? buf[cur][s] : NEGV;
            if (t < pl) {
                float lp   = g_lp_ext[(t * N_ + n) * S_ + s];
                float comb = lae(lae(a1, a2), a3);
                nv = valid ? (comb + lp) : NEGV;
            } else {
                nv = a1;   // inactive timestep keeps old alpha
            }
        }
        int nxt = cur ^ 1;
        if (s < S_) buf[nxt][s + 2] = nv;
        __syncthreads();
        cur = nxt;
    }

    if (s == 0) {
        int end = 2 * tl;
        float a_last = buf[cur][end + 2];
        float a_prev = (tl > 0) ? buf[cur][end + 1] : NEGV;
        float nll = -lae(a_last, a_prev);
        if (!isfinite(nll) || nll >= 1e29f) nll = 0.0f;
        int denom = tl > 0 ? tl : 1;
        g_per_n[n] = nll / (float)denom;
    }
}

// Kernel 3: mean over N
__global__ void __launch_bounds__(64) finalize_kernel(float* __restrict__ out)
{
    const int tid = threadIdx.x;
    float v = g_per_n[tid];
    #pragma unroll
    for (int o = 16; o > 0; o >>= 1) v += __shfl_xor_sync(0xffffffffu, v, o);
    __shared__ float sw[2];
    if ((tid & 31) == 0) sw[tid >> 5] = v;
    __syncthreads();
    if (tid == 0) out[0] = (sw[0] + sw[1]) / (float)N_;
}

extern "C" void kernel_launch(void* const* d_in, const int* in_sizes, int n_in,
                              void* d_out, int out_size)
{
    const float* preds          = (const float*)d_in[0];
    const int*   targets        = (const int*)d_in[1];
    const int*   pred_lengths   = (const int*)d_in[2];
    const int*   target_lengths = (const int*)d_in[3];
    float* out = (float*)d_out;

    lse_gather_kernel<<<T_ * N_, 256>>>(preds, targets);
    ctc_forward_kernel<<<N_, 96>>>(targets, pred_lengths, target_lengths);
    finalize_kernel<<<1, 64>>>(out);
}